// round 5
// baseline (speedup 1.0000x reference)
#include <cuda_runtime.h>
#include <math.h>

#define BB 16384
#define NN 20
#define DD 128
#define HH 4
#define SCALE 0.1020620726159658f /* 1/sqrt(96) */

typedef unsigned long long u64;

#define PK2(o, lo, hi) \
    asm("mov.b64 %0, {%1, %2};" : "=l"(o) : "r"(__float_as_uint(lo)), "r"(__float_as_uint(hi)))
#define FMA2A(d, a, b) \
    asm("fma.rn.f32x2 %0, %1, %2, %0;" : "+l"(d) : "l"(a), "l"(b))
#define UPK2(lo, hi, v) do { unsigned int _ul, _uh; \
    asm("mov.b64 {%0, %1}, %2;" : "=r"(_ul), "=r"(_uh) : "l"(v)); \
    lo = __uint_as_float(_ul); hi = __uint_as_float(_uh); } while (0)

// ---------------- device scratch ----------------
__device__ float g_qt[(size_t)BB * 1536];   // q-tilde [b][h*384+j]
__device__ float g_c [(size_t)BB * 1536];   // context [b][h*384+j]
__device__ float g_ao[(size_t)BB * 384];    // attn out pre-fc
__device__ float g_pre[(size_t)BB * 384];   // fc + bias + residual (pre-LN)
__device__ float g_WkT[4 * 384 * 96];       // [h][col j][k]

// ---------------- prep ----------------
__global__ void k_prep(const float* __restrict__ Wk) {
    int i = blockIdx.x * 256 + threadIdx.x;
    if (i < 147456) {
        int h = i / 36864, rem = i % 36864, col = rem / 96, k = rem % 96;
        g_WkT[i] = Wk[(h * 96 + k) * 384 + col];
    }
}

// ---------- GEMM tile: A pair-major [pair][kk] (u64 stride SPU, even), B transposed [col][kk] stride 36 ----------
// One ulonglong2 broadcast load gives a row-pair for 2 consecutive k-steps.
template<int NPAIR, int NCOL, int SPU>
__device__ __forceinline__ void gemm_tile(u64* acc, const float* saf, const float* sbt,
                                          int ct, int rt) {
    const u64* sa2 = (const u64*)saf;
    #pragma unroll
    for (int k4 = 0; k4 < 8; ++k4) {
        float bqa[NCOL][4];
        #pragma unroll
        for (int c = 0; c < NCOL; ++c)
            *(float4*)bqa[c] = *(const float4*)&sbt[(ct + 32 * c) * 36 + k4 * 4];
        #pragma unroll
        for (int k2 = 0; k2 < 2; ++k2) {
            const int kkb = k4 * 4 + k2 * 2;
            ulonglong2 av[NPAIR];
            #pragma unroll
            for (int p = 0; p < NPAIR; ++p)
                av[p] = *(const ulonglong2*)&sa2[(rt * NPAIR + p) * SPU + kkb];
            #pragma unroll
            for (int q = 0; q < 2; ++q) {
                u64 bp[NCOL];
                #pragma unroll
                for (int c = 0; c < NCOL; ++c) {
                    float bv = bqa[c][k2 * 2 + q];
                    PK2(bp[c], bv, bv);
                }
                #pragma unroll
                for (int p = 0; p < NPAIR; ++p) {
                    u64 ap = q ? av[p].y : av[p].x;
                    #pragma unroll
                    for (int c = 0; c < NCOL; ++c) FMA2A(acc[p * NCOL + c], ap, bp[c]);
                }
            }
        }
    }
}

// pair-major A staging index for (row = rt + 8j, kk = ct), pair stride 68 floats
// float_idx = (row>>1)*68 + ct*2 + (row&1) ; row>>1 = 4j + (rt>>1)
#define ABASE ((rt >> 1) * 68 + ct * 2 + (rt & 1))

// ---------------- q projection + q-tilde: block = (64-batch tile, head) ----------------
// dyn smem: saf[2][2176] | sbt[2][3456] | qs[6144] | sts[64]
__global__ void __launch_bounds__(256) k_qproj(const float* __restrict__ src,
                                               const float* __restrict__ src_ts,
                                               const float* __restrict__ freq,
                                               const float* __restrict__ phase,
                                               const float* __restrict__ Wq) {
    extern __shared__ __align__(16) float dynq[];
    float* saf[2] = { dynq, dynq + 2176 };
    float* sbt[2] = { dynq + 4352, dynq + 4352 + 3456 };
    float* qs  = dynq + 4352 + 6912;
    float* sts = qs + 6144;
    const int tid = threadIdx.x, ct = tid & 31, rt = tid >> 5;
    const int bt = blockIdx.x >> 2, h = blockIdx.x & 3, b0 = bt * 64;
    const int abase = ABASE;

    if (tid < 64) sts[tid] = src_ts[b0 + tid];
    __syncthreads();

    float areg[8]; float4 breg[3];

    #define LOAD_P1(KT) do {                                                     \
        const int m_ = (KT) + ct;                                                \
        _Pragma("unroll")                                                        \
        for (int j = 0; j < 8; ++j) {                                            \
            int row = rt + 8 * j;                                                \
            if (m_ < 128) areg[j] = src[(size_t)(b0 + row) * 128 + m_];          \
            else { int d_ = m_ - 128;                                            \
                   areg[j] = cosf(sts[row] * freq[d_] + phase[d_]); }            \
        }                                                                        \
        const int mp_ = ((KT) < 128 ? (KT) : (KT) + 128);                        \
        _Pragma("unroll")                                                        \
        for (int j = 0; j < 3; ++j) {                                            \
            int qidx = tid + 256 * j, col = qidx >> 3, q = qidx & 7;             \
            breg[j] = *(const float4*)&Wq[(size_t)(h * 96 + col) * 384 + mp_ + q * 4]; \
        } } while (0)
    #define STORE_AB(BUF) do {                                                   \
        _Pragma("unroll")                                                        \
        for (int j = 0; j < 8; ++j) saf[BUF][abase + 272 * j] = areg[j];         \
        _Pragma("unroll")                                                        \
        for (int j = 0; j < 3; ++j) {                                            \
            int qidx = tid + 256 * j, col = qidx >> 3, q = qidx & 7;             \
            *(float4*)&sbt[BUF][col * 36 + q * 4] = breg[j];                     \
        } } while (0)

    LOAD_P1(0); STORE_AB(0);
    __syncthreads();
    u64 acc[12] = {};
    for (int t = 0; t < 8; ++t) {
        const int cur = t & 1;
        if (t < 7) LOAD_P1((t + 1) * 32);
        gemm_tile<4, 3, 34>(acc, saf[cur], sbt[cur], ct, rt);
        if (t < 7) STORE_AB(cur ^ 1);
        __syncthreads();
    }
    #pragma unroll
    for (int p = 0; p < 4; ++p)
        #pragma unroll
        for (int c = 0; c < 3; ++c) {
            float lo, hi; UPK2(lo, hi, acc[p * 3 + c]);
            qs[(rt * 8 + 2 * p) * 96 + ct + 32 * c] = lo;
            qs[(rt * 8 + 2 * p + 1) * 96 + ct + 32 * c] = hi;
        }
    __syncthreads();

    // phase 2: qt(64x384) = qs(64x96) @ WkT_h
    for (int cp = 0; cp < 4; ++cp) {
        const int c0 = cp * 96;
        u64 a2[12] = {};
        for (int t = 0; t < 3; ++t) {
            const int kt = t * 32;
            __syncthreads();
            #pragma unroll
            for (int j = 0; j < 8; ++j)
                saf[0][abase + 272 * j] = qs[(rt + 8 * j) * 96 + kt + ct];
            #pragma unroll
            for (int j = 0; j < 3; ++j) {
                int qidx = tid + 256 * j, col = qidx >> 3, q = qidx & 7;
                *(float4*)&sbt[0][col * 36 + q * 4] =
                    *(const float4*)&g_WkT[(size_t)(h * 384 + c0 + col) * 96 + kt + q * 4];
            }
            __syncthreads();
            gemm_tile<4, 3, 34>(a2, saf[0], sbt[0], ct, rt);
        }
        #pragma unroll
        for (int p = 0; p < 4; ++p)
            #pragma unroll
            for (int c = 0; c < 3; ++c) {
                float lo, hi; UPK2(lo, hi, a2[p * 3 + c]);
                g_qt[(size_t)(b0 + rt * 8 + 2 * p) * 1536 + h * 384 + c0 + ct + 32 * c] = lo;
                g_qt[(size_t)(b0 + rt * 8 + 2 * p + 1) * 1536 + h * 384 + c0 + ct + 32 * c] = hi;
            }
    }
    #undef LOAD_P1
    #undef STORE_AB
}

// ---------------- attention core: one block per batch element ----------------
__global__ void __launch_bounds__(256) k_attn(const float* __restrict__ seq,
                                              const float* __restrict__ seq_e,
                                              const float* __restrict__ seq_ts,
                                              const unsigned int* __restrict__ mask,
                                              const float* __restrict__ freq,
                                              const float* __restrict__ phase,
                                              float* __restrict__ attn_out) {
    __shared__ float kin[NN * 384];
    __shared__ float qts[1536];
    __shared__ float sc[HH][NN];
    __shared__ float pp[HH][NN];
    const int b = blockIdx.x;
    const int tid = threadIdx.x;
    const int w = tid >> 5, lane = tid & 31;

    const float4* seq4   = (const float4*)seq;
    const float4* seq_e4 = (const float4*)seq_e;
    for (int idx = tid; idx < NN * 32; idx += 256) {
        int n = idx >> 5, q = idx & 31;
        float4 a = seq4  [((size_t)b * NN + n) * 32 + q];
        float4 e = seq_e4[((size_t)b * NN + n) * 32 + q];
        *(float4*)&kin[n * 384 + q * 4]       = a;
        *(float4*)&kin[n * 384 + 128 + q * 4] = e;
    }
    for (int idx = tid; idx < NN * 128; idx += 256) {
        int n = idx >> 7, d = idx & 127;
        kin[n * 384 + 256 + d] = cosf(seq_ts[b * NN + n] * freq[d] + phase[d]);
    }
    const float4* qt4 = (const float4*)(g_qt + (size_t)b * 1536);
    for (int idx = tid; idx < 384; idx += 256)
        *(float4*)&qts[idx * 4] = qt4[idx];
    __syncthreads();

    for (int p = w; p < HH * NN; p += 8) {
        int h = p / NN, n = p - h * NN;
        float partial = 0.f;
        #pragma unroll
        for (int t = 0; t < 12; ++t)
            partial = fmaf(qts[h * 384 + lane + 32 * t], kin[n * 384 + lane + 32 * t], partial);
        #pragma unroll
        for (int off = 16; off; off >>= 1)
            partial += __shfl_xor_sync(0xffffffffu, partial, off);
        if (lane == 0) {
            float s = partial * SCALE;
            if (mask[b * NN + n] != 0u) s = -1.0e10f;
            sc[h][n] = s;
        }
    }
    __syncthreads();

    if (w < HH) {
        float v = (lane < NN) ? sc[w][lane] : -3.0e38f;
        float mx = v;
        #pragma unroll
        for (int off = 16; off; off >>= 1)
            mx = fmaxf(mx, __shfl_xor_sync(0xffffffffu, mx, off));
        float e = (lane < NN) ? expf(v - mx) : 0.f;
        float s = e;
        #pragma unroll
        for (int off = 16; off; off >>= 1)
            s += __shfl_xor_sync(0xffffffffu, s, off);
        float prob = e / s;
        if (lane < NN) {
            pp[w][lane] = prob;
            attn_out[((size_t)w * BB + b) * NN + lane] = prob;
        }
    }
    __syncthreads();

    for (int idx = tid; idx < 1536; idx += 256) {
        int h = idx / 384, j = idx - h * 384;
        float s = 0.f;
        #pragma unroll
        for (int n = 0; n < NN; ++n)
            s = fmaf(pp[h][n], kin[n * 384 + j], s);
        g_c[(size_t)b * 1536 + idx] = s;
    }
}

// ---------------- Wv apply: block = (64-batch tile, head) ----------------
__global__ void __launch_bounds__(256) k_vout(const float* __restrict__ Wv) {
    __shared__ __align__(16) float saf[2][2176];
    __shared__ __align__(16) float sbt[2][96 * 36];
    const int tid = threadIdx.x, ct = tid & 31, rt = tid >> 5;
    const int bt = blockIdx.x >> 2, h = blockIdx.x & 3, b0 = bt * 64;
    const int abase = ABASE;

    float areg[8]; float4 breg[3];
    #define LOAD_V(KT) do {                                                          \
        _Pragma("unroll")                                                            \
        for (int j = 0; j < 8; ++j)                                                  \
            areg[j] = g_c[(size_t)(b0 + rt + 8 * j) * 1536 + h * 384 + (KT) + ct];   \
        _Pragma("unroll")                                                            \
        for (int j = 0; j < 3; ++j) {                                                \
            int qidx = tid + 256 * j, col = qidx >> 3, q = qidx & 7;                 \
            breg[j] = *(const float4*)&Wv[(size_t)(h * 96 + col) * 384 + (KT) + q * 4]; \
        } } while (0)
    #define STORE_V(BUF) do {                                                        \
        _Pragma("unroll")                                                            \
        for (int j = 0; j < 8; ++j) saf[BUF][abase + 272 * j] = areg[j];             \
        _Pragma("unroll")                                                            \
        for (int j = 0; j < 3; ++j) {                                                \
            int qidx = tid + 256 * j, col = qidx >> 3, q = qidx & 7;                 \
            *(float4*)&sbt[BUF][col * 36 + q * 4] = breg[j];                         \
        } } while (0)

    LOAD_V(0); STORE_V(0);
    __syncthreads();
    u64 acc[12] = {};
    for (int t = 0; t < 12; ++t) {
        const int cur = t & 1;
        if (t < 11) LOAD_V((t + 1) * 32);
        gemm_tile<4, 3, 34>(acc, saf[cur], sbt[cur], ct, rt);
        if (t < 11) STORE_V(cur ^ 1);
        __syncthreads();
    }
    #pragma unroll
    for (int p = 0; p < 4; ++p)
        #pragma unroll
        for (int c = 0; c < 3; ++c) {
            float lo, hi; UPK2(lo, hi, acc[p * 3 + c]);
            g_ao[(size_t)(b0 + rt * 8 + 2 * p) * 384 + h * 96 + ct + 32 * c] = lo;
            g_ao[(size_t)(b0 + rt * 8 + 2 * p + 1) * 384 + h * 96 + ct + 32 * c] = hi;
        }
    #undef LOAD_V
    #undef STORE_V
}

// ---------------- fc + bias + residual -> g_pre: block = (64-batch tile, col quarter) ----------------
__global__ void __launch_bounds__(256) k_fc(const float* __restrict__ src,
                                            const float* __restrict__ src_ts,
                                            const float* __restrict__ freq,
                                            const float* __restrict__ phase,
                                            const float* __restrict__ fc_w,
                                            const float* __restrict__ fc_b) {
    __shared__ __align__(16) float saf[2][2176];
    __shared__ __align__(16) float sbt[2][96 * 36];
    const int tid = threadIdx.x, ct = tid & 31, rt = tid >> 5;
    const int bt = blockIdx.x >> 2, cq = blockIdx.x & 3, b0 = bt * 64;
    const int c0 = cq * 96;
    const int abase = ABASE;

    float areg[8]; float4 breg[3];
    #define LOAD_F(KT) do {                                                          \
        _Pragma("unroll")                                                            \
        for (int j = 0; j < 8; ++j)                                                  \
            areg[j] = g_ao[(size_t)(b0 + rt + 8 * j) * 384 + (KT) + ct];             \
        _Pragma("unroll")                                                            \
        for (int j = 0; j < 3; ++j) {                                                \
            int qidx = tid + 256 * j, col = qidx >> 3, q = qidx & 7;                 \
            breg[j] = *(const float4*)&fc_w[(size_t)(c0 + col) * 384 + (KT) + q * 4]; \
        } } while (0)
    #define STORE_F(BUF) do {                                                        \
        _Pragma("unroll")                                                            \
        for (int j = 0; j < 8; ++j) saf[BUF][abase + 272 * j] = areg[j];             \
        _Pragma("unroll")                                                            \
        for (int j = 0; j < 3; ++j) {                                                \
            int qidx = tid + 256 * j, col = qidx >> 3, q = qidx & 7;                 \
            *(float4*)&sbt[BUF][col * 36 + q * 4] = breg[j];                         \
        } } while (0)

    LOAD_F(0); STORE_F(0);
    __syncthreads();
    u64 acc[12] = {};
    for (int t = 0; t < 12; ++t) {
        const int cur = t & 1;
        if (t < 11) LOAD_F((t + 1) * 32);
        gemm_tile<4, 3, 34>(acc, saf[cur], sbt[cur], ct, rt);
        if (t < 11) STORE_F(cur ^ 1);
        __syncthreads();
    }
    #pragma unroll
    for (int p = 0; p < 4; ++p)
        #pragma unroll
        for (int c = 0; c < 3; ++c) {
            float lo, hi; UPK2(lo, hi, acc[p * 3 + c]);
            const int col = c0 + ct + 32 * c;
            const int r0 = b0 + rt * 8 + 2 * p, r1 = r0 + 1;
            float add0 = fc_b[col], add1 = add0;
            if (col < 128) {
                add0 += src[(size_t)r0 * 128 + col];
                add1 += src[(size_t)r1 * 128 + col];
            } else if (col >= 256) {
                int d = col - 256;
                add0 += cosf(src_ts[r0] * freq[d] + phase[d]);
                add1 += cosf(src_ts[r1] * freq[d] + phase[d]);
            }
            g_pre[(size_t)r0 * 384 + col] = lo + add0;
            g_pre[(size_t)r1 * 384 + col] = hi + add1;
        }
    #undef LOAD_F
    #undef STORE_F
}

// ---------------- fused LN + MLP: 32 rows/block, pair-major A ----------------
// dyn smem: xs[16*1028] | hs[16*260] | sbt[128*36]
__global__ void __launch_bounds__(256) k_mlpln(const float* __restrict__ src,
                                               const float* __restrict__ ln_g,
                                               const float* __restrict__ ln_b,
                                               const float* __restrict__ m1_w,
                                               const float* __restrict__ m1_b,
                                               const float* __restrict__ m2_w,
                                               const float* __restrict__ m2_b,
                                               float* __restrict__ y) {
    extern __shared__ __align__(16) float dynm[];
    float* xs  = dynm;                // 16 pairs x 1028 floats (512 k, pair-major)
    float* hs  = xs + 16 * 1028;      // 16 pairs x 260 floats (128 k)
    float* sbt = hs + 16 * 260;       // 128 x 36
    const int tid = threadIdx.x, ct = tid & 31, rt = tid >> 5;
    const int b0 = blockIdx.x * 32;

    // stage [pre | src] pair-major: float idx = (r>>1)*1028 + k*2 + (r&1)
    for (int idx = tid; idx < 32 * 384; idx += 256) {
        int r = idx / 384, c = idx - r * 384;
        xs[(r >> 1) * 1028 + c * 2 + (r & 1)] = g_pre[(size_t)(b0 + r) * 384 + c];
    }
    for (int idx = tid; idx < 32 * 128; idx += 256) {
        int r = idx >> 7, d = idx & 127;
        xs[(r >> 1) * 1028 + (384 + d) * 2 + (r & 1)] = src[(size_t)(b0 + r) * 128 + d];
    }
    __syncthreads();

    // LayerNorm on k in [0,384): warp rt handles rows rt*4..rt*4+3
    for (int rr = 0; rr < 4; ++rr) {
        int row = rt * 4 + rr;
        float* xr = xs + (row >> 1) * 1028 + (row & 1);
        float s1 = 0.f, s2 = 0.f;
        #pragma unroll
        for (int t = 0; t < 12; ++t) {
            float v = xr[(ct + 32 * t) * 2];
            s1 += v; s2 = fmaf(v, v, s2);
        }
        #pragma unroll
        for (int off = 16; off; off >>= 1) {
            s1 += __shfl_xor_sync(0xffffffffu, s1, off);
            s2 += __shfl_xor_sync(0xffffffffu, s2, off);
        }
        float mu = s1 * (1.f / 384.f);
        float var = s2 * (1.f / 384.f) - mu * mu;
        float inv = rsqrtf(var + 1e-5f);
        #pragma unroll
        for (int t = 0; t < 12; ++t) {
            int j = ct + 32 * t;
            float v = xr[j * 2];
            xr[j * 2] = (v - mu) * inv * ln_g[j] + ln_b[j];
        }
    }

    float mb1[4], mb2[4];
    #pragma unroll
    for (int c = 0; c < 4; ++c) { mb1[c] = m1_b[ct + 32 * c]; mb2[c] = m2_b[ct + 32 * c]; }

    // GEMM1: h(32x128) = relu(x(32x512) @ m1_w^T + b), SPU=514
    u64 acc[8] = {};
    for (int t = 0; t < 16; ++t) {
        const int kt = t * 32;
        __syncthreads();
        #pragma unroll
        for (int j = 0; j < 4; ++j) {
            int qidx = tid + 256 * j, col = qidx >> 3, q = qidx & 7;
            *(float4*)&sbt[col * 36 + q * 4] =
                *(const float4*)&m1_w[(size_t)col * 512 + kt + q * 4];
        }
        __syncthreads();
        gemm_tile<2, 4, 514>(acc, xs + kt * 2, sbt, ct, rt);
    }
    __syncthreads();
    #pragma unroll
    for (int p = 0; p < 2; ++p)
        #pragma unroll
        for (int c = 0; c < 4; ++c) {
            float lo, hi; UPK2(lo, hi, acc[p * 4 + c]);
            int col = ct + 32 * c;
            hs[(rt * 2 + p) * 260 + col * 2]     = fmaxf(lo + mb1[c], 0.f);
            hs[(rt * 2 + p) * 260 + col * 2 + 1] = fmaxf(hi + mb1[c], 0.f);
        }

    // GEMM2: y = h(32x128) @ m2_w^T + b, SPU=130
    u64 a2[8] = {};
    for (int t = 0; t < 4; ++t) {
        const int kt = t * 32;
        __syncthreads();
        #pragma unroll
        for (int j = 0; j < 4; ++j) {
            int qidx = tid + 256 * j, col = qidx >> 3, q = qidx & 7;
            *(float4*)&sbt[col * 36 + q * 4] =
                *(const float4*)&m2_w[(size_t)col * 128 + kt + q * 4];
        }
        __syncthreads();
        gemm_tile<2, 4, 130>(a2, hs + kt * 2, sbt, ct, rt);
    }
    #pragma unroll
    for (int p = 0; p < 2; ++p)
        #pragma unroll
        for (int c = 0; c < 4; ++c) {
            float lo, hi; UPK2(lo, hi, a2[p * 4 + c]);
            int col = ct + 32 * c;
            y[(size_t)(b0 + rt * 4 + 2 * p) * 128 + col]     = lo + mb2[c];
            y[(size_t)(b0 + rt * 4 + 2 * p + 1) * 128 + col] = hi + mb2[c];
        }
}

// ---------------- launch ----------------
extern "C" void kernel_launch(void* const* d_in, const int* in_sizes, int n_in,
                              void* d_out, int out_size) {
    const float* src    = (const float*)d_in[0];
    const float* seq    = (const float*)d_in[1];
    const float* seq_e  = (const float*)d_in[2];
    const float* src_ts = (const float*)d_in[3];
    const float* seq_ts = (const float*)d_in[4];
    const unsigned int* mask = (const unsigned int*)d_in[5];
    const float* freq   = (const float*)d_in[6];
    const float* phase  = (const float*)d_in[7];
    const float* Wq     = (const float*)d_in[8];
    const float* Wk     = (const float*)d_in[9];
    const float* Wv     = (const float*)d_in[10];
    const float* fc_w   = (const float*)d_in[11];
    const float* fc_b   = (const float*)d_in[12];
    const float* ln_g   = (const float*)d_in[13];
    const float* ln_b   = (const float*)d_in[14];
    const float* m1_w   = (const float*)d_in[15];
    const float* m1_b   = (const float*)d_in[16];
    const float* m2_w   = (const float*)d_in[17];
    const float* m2_b   = (const float*)d_in[18];

    float* y_out = (float*)d_out;
    float* attn_out = y_out + (size_t)BB * DD;

    const int qproj_smem = (2176 * 2 + 3456 * 2 + 6144 + 64) * 4;   // 69888
    const int mlp_smem   = (16 * 1028 + 16 * 260 + 128 * 36) * 4;   // 100864
    cudaFuncSetAttribute(k_qproj, cudaFuncAttributeMaxDynamicSharedMemorySize, qproj_smem);
    cudaFuncSetAttribute(k_mlpln, cudaFuncAttributeMaxDynamicSharedMemorySize, mlp_smem);

    k_prep  <<<576, 256>>>(Wk);
    k_qproj <<<1024, 256, qproj_smem>>>(src, src_ts, freq, phase, Wq);
    k_attn  <<<BB, 256>>>(seq, seq_e, seq_ts, mask, freq, phase, attn_out);
    k_vout  <<<1024, 256>>>(Wv);
    k_fc    <<<1024, 256>>>(src, src_ts, freq, phase, fc_w, fc_b);
    k_mlpln <<<512, 256, mlp_smem>>>(src, ln_g, ln_b, m1_w, m1_b, m2_w, m2_b, y_out);
}

// round 6
// speedup vs baseline: 1.2382x; 1.2382x over previous
#include <cuda_runtime.h>
#include <math.h>

#define BB 16384
#define NN 20
#define DD 128
#define HH 4
#define SCALE 0.1020620726159658f /* 1/sqrt(96) */

typedef unsigned long long u64;

// ---------- scalar f32x2 helpers (MLP kernel) ----------
#define PK2(o, lo, hi) \
    asm("mov.b64 %0, {%1, %2};" : "=l"(o) : "r"(__float_as_uint(lo)), "r"(__float_as_uint(hi)))
#define FMA2A(d, a, b) \
    asm("fma.rn.f32x2 %0, %1, %2, %0;" : "+l"(d) : "l"(a), "l"(b))
#define UPK2(lo, hi, v) do { unsigned int _ul, _uh; \
    asm("mov.b64 {%0, %1}, %2;" : "=r"(_ul), "=r"(_uh) : "l"(v)); \
    lo = __uint_as_float(_ul); hi = __uint_as_float(_uh); } while (0)

// ---------------- device scratch ----------------
__device__ float g_qt[(size_t)BB * 1536];   // q-tilde
__device__ float g_c [(size_t)BB * 1536];   // context
__device__ float g_ao[(size_t)BB * 384];    // attn out pre-fc
__device__ float g_pre[(size_t)BB * 384];   // fc+bias+residual (pre-LN)
__device__ float g_Mqk[1536 * 256];         // fused Wq*Wk matrix [j][k]

__device__ __forceinline__ unsigned int tf32cvt(float x) {
    unsigned int u;
    asm("cvt.rna.tf32.f32 %0, %1;" : "=r"(u) : "f"(x));
    return u;
}

// ---------------- prep: M_qk[j][k] = sum_d Wq[h*96+d][keff] * Wk[h*96+d][jj] ----------------
__global__ void __launch_bounds__(256) k_prepm(const float* __restrict__ Wq,
                                               const float* __restrict__ Wk) {
    __shared__ float wk[8 * 96];
    const int tid = threadIdx.x;
    const int j0 = blockIdx.x * 8;       // 192 blocks
    const int h = j0 / 384;
    const int jj0 = j0 - h * 384;

    for (int i = tid; i < 768; i += 256) {
        int jo = i / 96, d = i - jo * 96;
        wk[jo * 96 + d] = Wk[(size_t)(h * 96 + d) * 384 + jj0 + jo];
    }
    __syncthreads();

    const int k = tid;                   // 0..255
    const int keff = (k < 128) ? k : k + 128;
    float acc[8] = {};
    for (int d = 0; d < 96; ++d) {
        float wq = __ldg(&Wq[(size_t)(h * 96 + d) * 384 + keff]);
        #pragma unroll
        for (int jo = 0; jo < 8; ++jo)
            acc[jo] = fmaf(wq, wk[jo * 96 + d], acc[jo]);
    }
    #pragma unroll
    for (int jo = 0; jo < 8; ++jo)
        g_Mqk[(size_t)(j0 + jo) * 256 + k] = acc[jo];
}

// ---------- warp-tile mma engine: 16 rows x 96 cols per warp over a 32-k smem tile ----------
// saf: [128 rows][stride 36] tf32 bits; sbt: [96 cols][stride 36] tf32 bits.
__device__ __forceinline__ void mma_tile32(float* acc, const float* saf, const float* sbt,
                                           int wid, int lane) {
    const int grp = lane >> 2, tig = lane & 3;
    #pragma unroll
    for (int sub = 0; sub < 4; ++sub) {
        const int kb = sub * 8;
        const float* ap = saf + (wid * 16 + grp) * 36 + kb + tig;
        unsigned int a0 = __float_as_uint(ap[0]);
        unsigned int a1 = __float_as_uint(ap[8 * 36]);
        unsigned int a2 = __float_as_uint(ap[4]);
        unsigned int a3 = __float_as_uint(ap[8 * 36 + 4]);
        #pragma unroll
        for (int nt = 0; nt < 12; ++nt) {
            const float* bp = sbt + (nt * 8 + grp) * 36 + kb + tig;
            unsigned int b0 = __float_as_uint(bp[0]);
            unsigned int b1 = __float_as_uint(bp[4]);
            float* c = acc + nt * 4;
            asm volatile(
                "mma.sync.aligned.m16n8k8.row.col.f32.tf32.tf32.f32 "
                "{%0,%1,%2,%3}, {%4,%5,%6,%7}, {%8,%9}, {%0,%1,%2,%3};"
                : "+f"(c[0]), "+f"(c[1]), "+f"(c[2]), "+f"(c[3])
                : "r"(a0), "r"(a1), "r"(a2), "r"(a3), "r"(b0), "r"(b1));
        }
    }
}

// B loader/stager shared shape: 3 float4 per thread from W[(colb+col)*KS + kt + q*4]
#define LOADB(W, COLB, KS, KT)                                                \
    _Pragma("unroll")                                                         \
    for (int jj = 0; jj < 3; ++jj) {                                          \
        int qidx = tid + 256 * jj, col = qidx >> 3, q = qidx & 7;             \
        breg[jj] = *(const float4*)&(W)[(size_t)((COLB) + col) * (KS) + (KT) + q * 4]; \
    }
#define STSB()                                                                \
    _Pragma("unroll")                                                         \
    for (int jj = 0; jj < 3; ++jj) {                                          \
        int qidx = tid + 256 * jj, col = qidx >> 3, q = qidx & 7;             \
        float4 v = breg[jj];                                                  \
        v.x = __uint_as_float(tf32cvt(v.x)); v.y = __uint_as_float(tf32cvt(v.y)); \
        v.z = __uint_as_float(tf32cvt(v.z)); v.w = __uint_as_float(tf32cvt(v.w)); \
        *(float4*)&sbt[col * 36 + q * 4] = v;                                 \
    }
#define STSA()                                                                \
    _Pragma("unroll")                                                         \
    for (int j = 0; j < 16; ++j)                                              \
        saf[(row0 + 8 * j) * 36 + kk] = __uint_as_float(tf32cvt(areg[j]));

// ---------------- k_qt: g_qt[B x 1536] = A_eff[B x 256] @ M_qk^T ----------------
__global__ void __launch_bounds__(256, 2) k_qt(const float* __restrict__ src,
                                               const float* __restrict__ src_ts,
                                               const float* __restrict__ freq,
                                               const float* __restrict__ phase) {
    __shared__ __align__(16) float saf[128 * 36];
    __shared__ __align__(16) float sbt[96 * 36];
    __shared__ float sts[128];
    const int tid = threadIdx.x, lane = tid & 31, wid = tid >> 5;
    const int bt = blockIdx.x >> 4, cq = blockIdx.x & 15;
    const int b0 = bt * 128, c0 = cq * 96;
    const int kk = tid & 31, row0 = tid >> 5;

    if (tid < 128) sts[tid] = src_ts[b0 + tid];
    __syncthreads();

    float areg[16]; float4 breg[3];
    #define LOADA_QT(KT) do {                                                 \
        int m = (KT) + kk;                                                    \
        if (m < 128) {                                                        \
            _Pragma("unroll")                                                 \
            for (int j = 0; j < 16; ++j)                                      \
                areg[j] = src[(size_t)(b0 + row0 + 8 * j) * 128 + m];         \
        } else {                                                              \
            float f = freq[m - 128], ph = phase[m - 128];                     \
            _Pragma("unroll")                                                 \
            for (int j = 0; j < 16; ++j)                                      \
                areg[j] = cosf(sts[row0 + 8 * j] * f + ph);                   \
        } } while (0)

    LOADA_QT(0); LOADB(g_Mqk, c0, 256, 0);
    float acc[48] = {};
    for (int t = 0; t < 8; ++t) {
        __syncthreads();
        STSA(); STSB();
        __syncthreads();
        if (t < 7) { LOADA_QT((t + 1) * 32); LOADB(g_Mqk, c0, 256, (t + 1) * 32); }
        mma_tile32(acc, saf, sbt, wid, lane);
    }
    const int grp = lane >> 2, tig = lane & 3;
    const int r0 = b0 + wid * 16 + grp;
    #pragma unroll
    for (int nt = 0; nt < 12; ++nt) {
        int j = c0 + nt * 8 + tig * 2;
        *(float2*)&g_qt[(size_t)r0 * 1536 + j]       = make_float2(acc[nt*4+0], acc[nt*4+1]);
        *(float2*)&g_qt[(size_t)(r0 + 8) * 1536 + j] = make_float2(acc[nt*4+2], acc[nt*4+3]);
    }
    #undef LOADA_QT
}

// ---------------- attention core: one block per batch element ----------------
__global__ void __launch_bounds__(256) k_attn(const float* __restrict__ seq,
                                              const float* __restrict__ seq_e,
                                              const float* __restrict__ seq_ts,
                                              const unsigned int* __restrict__ mask,
                                              const float* __restrict__ freq,
                                              const float* __restrict__ phase,
                                              float* __restrict__ attn_out) {
    __shared__ float kin[NN * 384];
    __shared__ float qts[1536];
    __shared__ float sc[HH][NN];
    __shared__ float pp[HH][NN];
    const int b = blockIdx.x;
    const int tid = threadIdx.x;
    const int w = tid >> 5, lane = tid & 31;

    const float4* seq4   = (const float4*)seq;
    const float4* seq_e4 = (const float4*)seq_e;
    for (int idx = tid; idx < NN * 32; idx += 256) {
        int n = idx >> 5, q = idx & 31;
        float4 a = seq4  [((size_t)b * NN + n) * 32 + q];
        float4 e = seq_e4[((size_t)b * NN + n) * 32 + q];
        *(float4*)&kin[n * 384 + q * 4]       = a;
        *(float4*)&kin[n * 384 + 128 + q * 4] = e;
    }
    for (int idx = tid; idx < NN * 128; idx += 256) {
        int n = idx >> 7, d = idx & 127;
        kin[n * 384 + 256 + d] = cosf(seq_ts[b * NN + n] * freq[d] + phase[d]);
    }
    const float4* qt4 = (const float4*)(g_qt + (size_t)b * 1536);
    for (int idx = tid; idx < 384; idx += 256)
        *(float4*)&qts[idx * 4] = qt4[idx];
    __syncthreads();

    for (int p = w; p < HH * NN; p += 8) {
        int h = p / NN, n = p - h * NN;
        float partial = 0.f;
        #pragma unroll
        for (int t = 0; t < 12; ++t)
            partial = fmaf(qts[h * 384 + lane + 32 * t], kin[n * 384 + lane + 32 * t], partial);
        #pragma unroll
        for (int off = 16; off; off >>= 1)
            partial += __shfl_xor_sync(0xffffffffu, partial, off);
        if (lane == 0) {
            float s = partial * SCALE;
            if (mask[b * NN + n] != 0u) s = -1.0e10f;
            sc[h][n] = s;
        }
    }
    __syncthreads();

    if (w < HH) {
        float v = (lane < NN) ? sc[w][lane] : -3.0e38f;
        float mx = v;
        #pragma unroll
        for (int off = 16; off; off >>= 1)
            mx = fmaxf(mx, __shfl_xor_sync(0xffffffffu, mx, off));
        float e = (lane < NN) ? expf(v - mx) : 0.f;
        float s = e;
        #pragma unroll
        for (int off = 16; off; off >>= 1)
            s += __shfl_xor_sync(0xffffffffu, s, off);
        float prob = e / s;
        if (lane < NN) {
            pp[w][lane] = prob;
            attn_out[((size_t)w * BB + b) * NN + lane] = prob;
        }
    }
    __syncthreads();

    for (int idx = tid; idx < 1536; idx += 256) {
        int h = idx / 384, j = idx - h * 384;
        float s = 0.f;
        #pragma unroll
        for (int n = 0; n < NN; ++n)
            s = fmaf(pp[h][n], kin[n * 384 + j], s);
        g_c[(size_t)b * 1536 + idx] = s;
    }
}

// ---------------- k_vout: g_ao head slab = g_c_h[B x 384] @ Wv_h^T ----------------
__global__ void __launch_bounds__(256, 2) k_vout(const float* __restrict__ Wv) {
    __shared__ __align__(16) float saf[128 * 36];
    __shared__ __align__(16) float sbt[96 * 36];
    const int tid = threadIdx.x, lane = tid & 31, wid = tid >> 5;
    const int bt = blockIdx.x >> 2, h = blockIdx.x & 3;
    const int b0 = bt * 128;
    const int kk = tid & 31, row0 = tid >> 5;

    float areg[16]; float4 breg[3];
    #define LOADA_V(KT)                                                        \
        _Pragma("unroll")                                                      \
        for (int j = 0; j < 16; ++j)                                           \
            areg[j] = g_c[(size_t)(b0 + row0 + 8 * j) * 1536 + h * 384 + (KT) + kk];

    LOADA_V(0); LOADB(Wv, h * 96, 384, 0);
    float acc[48] = {};
    for (int t = 0; t < 12; ++t) {
        __syncthreads();
        STSA(); STSB();
        __syncthreads();
        if (t < 11) { LOADA_V((t + 1) * 32); LOADB(Wv, h * 96, 384, (t + 1) * 32); }
        mma_tile32(acc, saf, sbt, wid, lane);
    }
    const int grp = lane >> 2, tig = lane & 3;
    const int r0 = b0 + wid * 16 + grp;
    #pragma unroll
    for (int nt = 0; nt < 12; ++nt) {
        int col = h * 96 + nt * 8 + tig * 2;
        *(float2*)&g_ao[(size_t)r0 * 384 + col]       = make_float2(acc[nt*4+0], acc[nt*4+1]);
        *(float2*)&g_ao[(size_t)(r0 + 8) * 384 + col] = make_float2(acc[nt*4+2], acc[nt*4+3]);
    }
    #undef LOADA_V
}

// ---------------- k_fc: g_pre = g_ao @ fc_w^T + b + residual ----------------
__global__ void __launch_bounds__(256, 2) k_fc(const float* __restrict__ src,
                                               const float* __restrict__ src_ts,
                                               const float* __restrict__ freq,
                                               const float* __restrict__ phase,
                                               const float* __restrict__ fc_w,
                                               const float* __restrict__ fc_b) {
    __shared__ __align__(16) float saf[128 * 36];
    __shared__ __align__(16) float sbt[96 * 36];
    const int tid = threadIdx.x, lane = tid & 31, wid = tid >> 5;
    const int bt = blockIdx.x >> 2, cq = blockIdx.x & 3;
    const int b0 = bt * 128, c0 = cq * 96;
    const int kk = tid & 31, row0 = tid >> 5;

    float areg[16]; float4 breg[3];
    #define LOADA_F(KT)                                                        \
        _Pragma("unroll")                                                      \
        for (int j = 0; j < 16; ++j)                                           \
            areg[j] = g_ao[(size_t)(b0 + row0 + 8 * j) * 384 + (KT) + kk];

    LOADA_F(0); LOADB(fc_w, c0, 384, 0);
    float acc[48] = {};
    for (int t = 0; t < 12; ++t) {
        __syncthreads();
        STSA(); STSB();
        __syncthreads();
        if (t < 11) { LOADA_F((t + 1) * 32); LOADB(fc_w, c0, 384, (t + 1) * 32); }
        mma_tile32(acc, saf, sbt, wid, lane);
    }
    const int grp = lane >> 2, tig = lane & 3;
    const int r0 = b0 + wid * 16 + grp;
    const float ts0 = src_ts[r0], ts1 = src_ts[r0 + 8];
    #pragma unroll
    for (int nt = 0; nt < 12; ++nt) {
        #pragma unroll
        for (int cc = 0; cc < 2; ++cc) {
            int col = c0 + nt * 8 + tig * 2 + cc;
            float v0 = acc[nt*4 + cc]     + fc_b[col];
            float v1 = acc[nt*4 + 2 + cc] + fc_b[col];
            if (col < 128) {
                v0 += src[(size_t)r0 * 128 + col];
                v1 += src[(size_t)(r0 + 8) * 128 + col];
            } else if (col >= 256) {
                int d = col - 256;
                float f = freq[d], ph = phase[d];
                v0 += cosf(ts0 * f + ph);
                v1 += cosf(ts1 * f + ph);
            }
            g_pre[(size_t)r0 * 384 + col]       = v0;
            g_pre[(size_t)(r0 + 8) * 384 + col] = v1;
        }
    }
    #undef LOADA_F
}

// ---------- scalar tile engine (MLP) ----------
template<int NPAIR, int NCOL, int SPU>
__device__ __forceinline__ void gemm_tile(u64* acc, const float* saf, const float* sbt,
                                          int ct, int rt) {
    const u64* sa2 = (const u64*)saf;
    #pragma unroll
    for (int k4 = 0; k4 < 8; ++k4) {
        float bqa[NCOL][4];
        #pragma unroll
        for (int c = 0; c < NCOL; ++c)
            *(float4*)bqa[c] = *(const float4*)&sbt[(ct + 32 * c) * 36 + k4 * 4];
        #pragma unroll
        for (int k2 = 0; k2 < 2; ++k2) {
            const int kkb = k4 * 4 + k2 * 2;
            ulonglong2 av[NPAIR];
            #pragma unroll
            for (int p = 0; p < NPAIR; ++p)
                av[p] = *(const ulonglong2*)&sa2[(rt * NPAIR + p) * SPU + kkb];
            #pragma unroll
            for (int q = 0; q < 2; ++q) {
                u64 bp[NCOL];
                #pragma unroll
                for (int c = 0; c < NCOL; ++c) {
                    float bv = bqa[c][k2 * 2 + q];
                    PK2(bp[c], bv, bv);
                }
                #pragma unroll
                for (int p = 0; p < NPAIR; ++p) {
                    u64 ap = q ? av[p].y : av[p].x;
                    #pragma unroll
                    for (int c = 0; c < NCOL; ++c) FMA2A(acc[p * NCOL + c], ap, bp[c]);
                }
            }
        }
    }
}

// ---------------- fused LN + MLP: 32 rows/block, pair-major A ----------------
__global__ void __launch_bounds__(256) k_mlpln(const float* __restrict__ src,
                                               const float* __restrict__ ln_g,
                                               const float* __restrict__ ln_b,
                                               const float* __restrict__ m1_w,
                                               const float* __restrict__ m1_b,
                                               const float* __restrict__ m2_w,
                                               const float* __restrict__ m2_b,
                                               float* __restrict__ y) {
    extern __shared__ __align__(16) float dynm[];
    float* xs  = dynm;                // 16 pairs x 1028
    float* hs  = xs + 16 * 1028;      // 16 pairs x 260
    float* sbt = hs + 16 * 260;       // 128 x 36
    const int tid = threadIdx.x, ct = tid & 31, rt = tid >> 5;
    const int b0 = blockIdx.x * 32;

    for (int idx = tid; idx < 32 * 384; idx += 256) {
        int r = idx / 384, c = idx - r * 384;
        xs[(r >> 1) * 1028 + c * 2 + (r & 1)] = g_pre[(size_t)(b0 + r) * 384 + c];
    }
    for (int idx = tid; idx < 32 * 128; idx += 256) {
        int r = idx >> 7, d = idx & 127;
        xs[(r >> 1) * 1028 + (384 + d) * 2 + (r & 1)] = src[(size_t)(b0 + r) * 128 + d];
    }
    __syncthreads();

    for (int rr = 0; rr < 4; ++rr) {
        int row = rt * 4 + rr;
        float* xr = xs + (row >> 1) * 1028 + (row & 1);
        float s1 = 0.f, s2 = 0.f;
        #pragma unroll
        for (int t = 0; t < 12; ++t) {
            float v = xr[(ct + 32 * t) * 2];
            s1 += v; s2 = fmaf(v, v, s2);
        }
        #pragma unroll
        for (int off = 16; off; off >>= 1) {
            s1 += __shfl_xor_sync(0xffffffffu, s1, off);
            s2 += __shfl_xor_sync(0xffffffffu, s2, off);
        }
        float mu = s1 * (1.f / 384.f);
        float var = s2 * (1.f / 384.f) - mu * mu;
        float inv = rsqrtf(var + 1e-5f);
        #pragma unroll
        for (int t = 0; t < 12; ++t) {
            int j = ct + 32 * t;
            float v = xr[j * 2];
            xr[j * 2] = (v - mu) * inv * ln_g[j] + ln_b[j];
        }
    }

    float mb1[4], mb2[4];
    #pragma unroll
    for (int c = 0; c < 4; ++c) { mb1[c] = m1_b[ct + 32 * c]; mb2[c] = m2_b[ct + 32 * c]; }

    u64 acc[8] = {};
    for (int t = 0; t < 16; ++t) {
        const int kt = t * 32;
        __syncthreads();
        #pragma unroll
        for (int j = 0; j < 4; ++j) {
            int qidx = tid + 256 * j, col = qidx >> 3, q = qidx & 7;
            *(float4*)&sbt[col * 36 + q * 4] =
                *(const float4*)&m1_w[(size_t)col * 512 + kt + q * 4];
        }
        __syncthreads();
        gemm_tile<2, 4, 514>(acc, xs + kt * 2, sbt, ct, rt);
    }
    __syncthreads();
    #pragma unroll
    for (int p = 0; p < 2; ++p)
        #pragma unroll
        for (int c = 0; c < 4; ++c) {
            float lo, hi; UPK2(lo, hi, acc[p * 4 + c]);
            int col = ct + 32 * c;
            hs[(rt * 2 + p) * 260 + col * 2]     = fmaxf(lo + mb1[c], 0.f);
            hs[(rt * 2 + p) * 260 + col * 2 + 1] = fmaxf(hi + mb1[c], 0.f);
        }

    u64 a2[8] = {};
    for (int t = 0; t < 4; ++t) {
        const int kt = t * 32;
        __syncthreads();
        #pragma unroll
        for (int j = 0; j < 4; ++j) {
            int qidx = tid + 256 * j, col = qidx >> 3, q = qidx & 7;
            *(float4*)&sbt[col * 36 + q * 4] =
                *(const float4*)&m2_w[(size_t)col * 128 + kt + q * 4];
        }
        __syncthreads();
        gemm_tile<2, 4, 130>(a2, hs + kt * 2, sbt, ct, rt);
    }
    #pragma unroll
    for (int p = 0; p < 2; ++p)
        #pragma unroll
        for (int c = 0; c < 4; ++c) {
            float lo, hi; UPK2(lo, hi, a2[p * 4 + c]);
            int col = ct + 32 * c;
            y[(size_t)(b0 + rt * 4 + 2 * p) * 128 + col]     = lo + mb2[c];
            y[(size_t)(b0 + rt * 4 + 2 * p + 1) * 128 + col] = hi + mb2[c];
        }
}

// ---------------- launch ----------------
extern "C" void kernel_launch(void* const* d_in, const int* in_sizes, int n_in,
                              void* d_out, int out_size) {
    const float* src    = (const float*)d_in[0];
    const float* seq    = (const float*)d_in[1];
    const float* seq_e  = (const float*)d_in[2];
    const float* src_ts = (const float*)d_in[3];
    const float* seq_ts = (const float*)d_in[4];
    const unsigned int* mask = (const unsigned int*)d_in[5];
    const float* freq   = (const float*)d_in[6];
    const float* phase  = (const float*)d_in[7];
    const float* Wq     = (const float*)d_in[8];
    const float* Wk     = (const float*)d_in[9];
    const float* Wv     = (const float*)d_in[10];
    const float* fc_w   = (const float*)d_in[11];
    const float* fc_b   = (const float*)d_in[12];
    const float* ln_g   = (const float*)d_in[13];
    const float* ln_b   = (const float*)d_in[14];
    const float* m1_w   = (const float*)d_in[15];
    const float* m1_b   = (const float*)d_in[16];
    const float* m2_w   = (const float*)d_in[17];
    const float* m2_b   = (const float*)d_in[18];

    float* y_out = (float*)d_out;
    float* attn_out = y_out + (size_t)BB * DD;

    const int mlp_smem = (16 * 1028 + 16 * 260 + 128 * 36) * 4;   // 100864
    cudaFuncSetAttribute(k_mlpln, cudaFuncAttributeMaxDynamicSharedMemorySize, mlp_smem);

    k_prepm <<<192, 256>>>(Wq, Wk);
    k_qt    <<<2048, 256>>>(src, src_ts, freq, phase);
    k_attn  <<<BB, 256>>>(seq, seq_e, seq_ts, mask, freq, phase, attn_out);
    k_vout  <<<512, 256>>>(Wv);
    k_fc    <<<512, 256>>>(src, src_ts, freq, phase, fc_w, fc_b);
    k_mlpln <<<512, 256, mlp_smem>>>(src, ln_g, ln_b, m1_w, m1_b, m2_w, m2_b, y_out);
}

// round 7
// speedup vs baseline: 1.4712x; 1.1881x over previous
#include <cuda_runtime.h>
#include <math.h>

#define BB 16384
#define NN 20
#define DD 128
#define HH 4
#define SCALE 0.1020620726159658f /* 1/sqrt(96) */

// ---------------- device scratch ----------------
__device__ float g_qt[(size_t)BB * 1536];   // q-tilde
__device__ float g_c [(size_t)BB * 1536];   // context
__device__ float g_ao[(size_t)BB * 384];    // attn out pre-fc
__device__ float g_pre[(size_t)BB * 384];   // fc+bias+residual (pre-LN)
__device__ float g_Mqk[1536 * 256];         // fused Wq*Wk matrix [j][k]

__device__ __forceinline__ unsigned int tf32cvt(float x) {
    unsigned int u;
    asm("cvt.rna.tf32.f32 %0, %1;" : "=r"(u) : "f"(x));
    return u;
}

// ---------------- prep: M_qk[j][k] = sum_d Wq[h*96+d][keff] * Wk[h*96+d][jj] ----------------
__global__ void __launch_bounds__(256) k_prepm(const float* __restrict__ Wq,
                                               const float* __restrict__ Wk) {
    __shared__ float wk[8 * 96];
    const int tid = threadIdx.x;
    const int j0 = blockIdx.x * 8;       // 192 blocks
    const int h = j0 / 384;
    const int jj0 = j0 - h * 384;

    for (int i = tid; i < 768; i += 256) {
        int jo = i / 96, d = i - jo * 96;
        wk[jo * 96 + d] = Wk[(size_t)(h * 96 + d) * 384 + jj0 + jo];
    }
    __syncthreads();

    const int k = tid;
    const int keff = (k < 128) ? k : k + 128;
    float acc[8] = {};
    for (int d = 0; d < 96; ++d) {
        float wq = __ldg(&Wq[(size_t)(h * 96 + d) * 384 + keff]);
        #pragma unroll
        for (int jo = 0; jo < 8; ++jo)
            acc[jo] = fmaf(wq, wk[jo * 96 + d], acc[jo]);
    }
    #pragma unroll
    for (int jo = 0; jo < 8; ++jo)
        g_Mqk[(size_t)(j0 + jo) * 256 + k] = acc[jo];
}

// ---------- warp mma engine: 16 rows x NT*8 cols over a 32-k smem tile ----------
// sa_slab: warp's A rows [16][stride 36]; sbt: B cols [..][stride 36] (tf32 bits)
template<int NT>
__device__ __forceinline__ void mma_warp(float* acc, const float* sa_slab, const float* sbt,
                                         int lane) {
    const int grp = lane >> 2, tig = lane & 3;
    #pragma unroll
    for (int sub = 0; sub < 4; ++sub) {
        const int kb = sub * 8;
        const float* ap = sa_slab + grp * 36 + kb + tig;
        unsigned int a0 = __float_as_uint(ap[0]);
        unsigned int a1 = __float_as_uint(ap[8 * 36]);
        unsigned int a2 = __float_as_uint(ap[4]);
        unsigned int a3 = __float_as_uint(ap[8 * 36 + 4]);
        #pragma unroll
        for (int nt = 0; nt < NT; ++nt) {
            const float* bp = sbt + (nt * 8 + grp) * 36 + kb + tig;
            unsigned int b0 = __float_as_uint(bp[0]);
            unsigned int b1 = __float_as_uint(bp[4]);
            float* c = acc + nt * 4;
            asm volatile(
                "mma.sync.aligned.m16n8k8.row.col.f32.tf32.tf32.f32 "
                "{%0,%1,%2,%3}, {%4,%5,%6,%7}, {%8,%9}, {%0,%1,%2,%3};"
                : "+f"(c[0]), "+f"(c[1]), "+f"(c[2]), "+f"(c[3])
                : "r"(a0), "r"(a1), "r"(a2), "r"(a3), "r"(b0), "r"(b1));
        }
    }
}

// B loader/stager: 96 cols variant (3 float4/thread)
#define LOADB(W, COLB, KS, KT)                                                \
    _Pragma("unroll")                                                         \
    for (int jj = 0; jj < 3; ++jj) {                                          \
        int qidx = tid + 256 * jj, col = qidx >> 3, q = qidx & 7;             \
        breg[jj] = *(const float4*)&(W)[(size_t)((COLB) + col) * (KS) + (KT) + q * 4]; \
    }
#define STSB()                                                                \
    _Pragma("unroll")                                                         \
    for (int jj = 0; jj < 3; ++jj) {                                          \
        int qidx = tid + 256 * jj, col = qidx >> 3, q = qidx & 7;             \
        float4 v = breg[jj];                                                  \
        v.x = __uint_as_float(tf32cvt(v.x)); v.y = __uint_as_float(tf32cvt(v.y)); \
        v.z = __uint_as_float(tf32cvt(v.z)); v.w = __uint_as_float(tf32cvt(v.w)); \
        *(float4*)&sbt[col * 36 + q * 4] = v;                                 \
    }
#define STSA()                                                                \
    _Pragma("unroll")                                                         \
    for (int j = 0; j < 16; ++j)                                              \
        saf[(row0 + 8 * j) * 36 + kk] = __uint_as_float(tf32cvt(areg[j]));

// ---------------- k_qt: g_qt[B x 1536] = A_eff[B x 256] @ M_qk^T ----------------
__global__ void __launch_bounds__(256, 2) k_qt(const float* __restrict__ src,
                                               const float* __restrict__ src_ts,
                                               const float* __restrict__ freq,
                                               const float* __restrict__ phase) {
    __shared__ __align__(16) float saf[128 * 36];
    __shared__ __align__(16) float sbt[96 * 36];
    __shared__ float sts[128];
    const int tid = threadIdx.x, lane = tid & 31, wid = tid >> 5;
    const int bt = blockIdx.x >> 4, cq = blockIdx.x & 15;
    const int b0 = bt * 128, c0 = cq * 96;
    const int kk = tid & 31, row0 = tid >> 5;

    if (tid < 128) sts[tid] = src_ts[b0 + tid];
    __syncthreads();

    float areg[16]; float4 breg[3];
    #define LOADA_QT(KT) do {                                                 \
        int m = (KT) + kk;                                                    \
        if (m < 128) {                                                        \
            _Pragma("unroll")                                                 \
            for (int j = 0; j < 16; ++j)                                      \
                areg[j] = src[(size_t)(b0 + row0 + 8 * j) * 128 + m];         \
        } else {                                                              \
            float f = freq[m - 128], ph = phase[m - 128];                     \
            _Pragma("unroll")                                                 \
            for (int j = 0; j < 16; ++j)                                      \
                areg[j] = __cosf(sts[row0 + 8 * j] * f + ph);                 \
        } } while (0)

    LOADA_QT(0); LOADB(g_Mqk, c0, 256, 0);
    float acc[48] = {};
    for (int t = 0; t < 8; ++t) {
        __syncthreads();
        STSA(); STSB();
        __syncthreads();
        if (t < 7) { LOADA_QT((t + 1) * 32); LOADB(g_Mqk, c0, 256, (t + 1) * 32); }
        mma_warp<12>(acc, saf + wid * 16 * 36, sbt, lane);
    }
    const int grp = lane >> 2, tig = lane & 3;
    const int r0 = b0 + wid * 16 + grp;
    #pragma unroll
    for (int nt = 0; nt < 12; ++nt) {
        int j = c0 + nt * 8 + tig * 2;
        *(float2*)&g_qt[(size_t)r0 * 1536 + j]       = make_float2(acc[nt*4+0], acc[nt*4+1]);
        *(float2*)&g_qt[(size_t)(r0 + 8) * 1536 + j] = make_float2(acc[nt*4+2], acc[nt*4+3]);
    }
    #undef LOADA_QT
}

// ---------------- attention core: one block per batch element ----------------
__global__ void __launch_bounds__(256) k_attn(const float* __restrict__ seq,
                                              const float* __restrict__ seq_e,
                                              const float* __restrict__ seq_ts,
                                              const unsigned int* __restrict__ mask,
                                              const float* __restrict__ freq,
                                              const float* __restrict__ phase,
                                              float* __restrict__ attn_out) {
    __shared__ float kin[NN * 384];
    __shared__ float qts[1536];
    __shared__ float sc[HH][NN];
    __shared__ float pp[HH][NN];
    const int b = blockIdx.x;
    const int tid = threadIdx.x;
    const int w = tid >> 5, lane = tid & 31;

    const float4* seq4   = (const float4*)seq;
    const float4* seq_e4 = (const float4*)seq_e;
    for (int idx = tid; idx < NN * 32; idx += 256) {
        int n = idx >> 5, q = idx & 31;
        float4 a = seq4  [((size_t)b * NN + n) * 32 + q];
        float4 e = seq_e4[((size_t)b * NN + n) * 32 + q];
        *(float4*)&kin[n * 384 + q * 4]       = a;
        *(float4*)&kin[n * 384 + 128 + q * 4] = e;
    }
    for (int idx = tid; idx < NN * 128; idx += 256) {
        int n = idx >> 7, d = idx & 127;
        kin[n * 384 + 256 + d] = __cosf(seq_ts[b * NN + n] * freq[d] + phase[d]);
    }
    const float4* qt4 = (const float4*)(g_qt + (size_t)b * 1536);
    for (int idx = tid; idx < 384; idx += 256)
        *(float4*)&qts[idx * 4] = qt4[idx];
    __syncthreads();

    for (int p = w; p < HH * NN; p += 8) {
        int h = p / NN, n = p - h * NN;
        float partial = 0.f;
        #pragma unroll
        for (int t = 0; t < 12; ++t)
            partial = fmaf(qts[h * 384 + lane + 32 * t], kin[n * 384 + lane + 32 * t], partial);
        #pragma unroll
        for (int off = 16; off; off >>= 1)
            partial += __shfl_xor_sync(0xffffffffu, partial, off);
        if (lane == 0) {
            float s = partial * SCALE;
            if (mask[b * NN + n] != 0u) s = -1.0e10f;
            sc[h][n] = s;
        }
    }
    __syncthreads();

    if (w < HH) {
        float v = (lane < NN) ? sc[w][lane] : -3.0e38f;
        float mx = v;
        #pragma unroll
        for (int off = 16; off; off >>= 1)
            mx = fmaxf(mx, __shfl_xor_sync(0xffffffffu, mx, off));
        float e = (lane < NN) ? expf(v - mx) : 0.f;
        float s = e;
        #pragma unroll
        for (int off = 16; off; off >>= 1)
            s += __shfl_xor_sync(0xffffffffu, s, off);
        float prob = e / s;
        if (lane < NN) {
            pp[w][lane] = prob;
            attn_out[((size_t)w * BB + b) * NN + lane] = prob;
        }
    }
    __syncthreads();

    for (int idx = tid; idx < 1536; idx += 256) {
        int h = idx / 384, j = idx - h * 384;
        float s = 0.f;
        #pragma unroll
        for (int n = 0; n < NN; ++n)
            s = fmaf(pp[h][n], kin[n * 384 + j], s);
        g_c[(size_t)b * 1536 + idx] = s;
    }
}

// ---------------- k_vout: g_ao head slab = g_c_h[B x 384] @ Wv_h^T ----------------
__global__ void __launch_bounds__(256, 2) k_vout(const float* __restrict__ Wv) {
    __shared__ __align__(16) float saf[128 * 36];
    __shared__ __align__(16) float sbt[96 * 36];
    const int tid = threadIdx.x, lane = tid & 31, wid = tid >> 5;
    const int bt = blockIdx.x >> 2, h = blockIdx.x & 3;
    const int b0 = bt * 128;
    const int kk = tid & 31, row0 = tid >> 5;

    float areg[16]; float4 breg[3];
    #define LOADA_V(KT)                                                        \
        _Pragma("unroll")                                                      \
        for (int j = 0; j < 16; ++j)                                           \
            areg[j] = g_c[(size_t)(b0 + row0 + 8 * j) * 1536 + h * 384 + (KT) + kk];

    LOADA_V(0); LOADB(Wv, h * 96, 384, 0);
    float acc[48] = {};
    for (int t = 0; t < 12; ++t) {
        __syncthreads();
        STSA(); STSB();
        __syncthreads();
        if (t < 11) { LOADA_V((t + 1) * 32); LOADB(Wv, h * 96, 384, (t + 1) * 32); }
        mma_warp<12>(acc, saf + wid * 16 * 36, sbt, lane);
    }
    const int grp = lane >> 2, tig = lane & 3;
    const int r0 = b0 + wid * 16 + grp;
    #pragma unroll
    for (int nt = 0; nt < 12; ++nt) {
        int col = h * 96 + nt * 8 + tig * 2;
        *(float2*)&g_ao[(size_t)r0 * 384 + col]       = make_float2(acc[nt*4+0], acc[nt*4+1]);
        *(float2*)&g_ao[(size_t)(r0 + 8) * 384 + col] = make_float2(acc[nt*4+2], acc[nt*4+3]);
    }
    #undef LOADA_V
}

// ---------------- k_fc: g_pre = g_ao @ fc_w^T + b + residual ----------------
__global__ void __launch_bounds__(256, 2) k_fc(const float* __restrict__ src,
                                               const float* __restrict__ src_ts,
                                               const float* __restrict__ freq,
                                               const float* __restrict__ phase,
                                               const float* __restrict__ fc_w,
                                               const float* __restrict__ fc_b) {
    __shared__ __align__(16) float saf[128 * 36];
    __shared__ __align__(16) float sbt[96 * 36];
    const int tid = threadIdx.x, lane = tid & 31, wid = tid >> 5;
    const int bt = blockIdx.x >> 2, cq = blockIdx.x & 3;
    const int b0 = bt * 128, c0 = cq * 96;
    const int kk = tid & 31, row0 = tid >> 5;

    float areg[16]; float4 breg[3];
    #define LOADA_F(KT)                                                        \
        _Pragma("unroll")                                                      \
        for (int j = 0; j < 16; ++j)                                           \
            areg[j] = g_ao[(size_t)(b0 + row0 + 8 * j) * 384 + (KT) + kk];

    LOADA_F(0); LOADB(fc_w, c0, 384, 0);
    float acc[48] = {};
    for (int t = 0; t < 12; ++t) {
        __syncthreads();
        STSA(); STSB();
        __syncthreads();
        if (t < 11) { LOADA_F((t + 1) * 32); LOADB(fc_w, c0, 384, (t + 1) * 32); }
        mma_warp<12>(acc, saf + wid * 16 * 36, sbt, lane);
    }
    const int grp = lane >> 2, tig = lane & 3;
    const int r0 = b0 + wid * 16 + grp;
    const float ts0 = src_ts[r0], ts1 = src_ts[r0 + 8];
    #pragma unroll
    for (int nt = 0; nt < 12; ++nt) {
        #pragma unroll
        for (int cc = 0; cc < 2; ++cc) {
            int col = c0 + nt * 8 + tig * 2 + cc;
            float v0 = acc[nt*4 + cc]     + fc_b[col];
            float v1 = acc[nt*4 + 2 + cc] + fc_b[col];
            if (col < 128) {
                v0 += src[(size_t)r0 * 128 + col];
                v1 += src[(size_t)(r0 + 8) * 128 + col];
            } else if (col >= 256) {
                int d = col - 256;
                float f = freq[d], ph = phase[d];
                v0 += __cosf(ts0 * f + ph);
                v1 += __cosf(ts1 * f + ph);
            }
            g_pre[(size_t)r0 * 384 + col]       = v0;
            g_pre[(size_t)(r0 + 8) * 384 + col] = v1;
        }
    }
    #undef LOADA_F
}

// ---------------- k_mlp: two-pass LN + tensor-core MLP, 64 rows/block ----------------
// warp w: rows (w>>1)*16..+16, cols (w&1)*64..+64 (NT=8)
// dyn smem: saf[64*36] | sbt[128*36] | hst[4][64*36] | smu[64] | sinv[64]
__global__ void __launch_bounds__(256) k_mlp(const float* __restrict__ src,
                                             const float* __restrict__ ln_g,
                                             const float* __restrict__ ln_b,
                                             const float* __restrict__ m1_w,
                                             const float* __restrict__ m1_b,
                                             const float* __restrict__ m2_w,
                                             const float* __restrict__ m2_b,
                                             float* __restrict__ y) {
    extern __shared__ __align__(16) float dynm[];
    float* saf  = dynm;                 // 2304
    float* sbt  = saf + 64 * 36;        // 4608
    float* hst  = sbt + 128 * 36;       // 4 x 2304
    float* smu  = hst + 4 * 2304;       // 64
    float* sinv = smu + 64;             // 64
    const int tid = threadIdx.x, lane = tid & 31, wid = tid >> 5;
    const int b0 = blockIdx.x * 64;
    const int kk = tid & 31, row0 = tid >> 5;

    // pass 1: per-row LN stats (warp wid -> rows wid*8..+7)
    for (int rr = 0; rr < 8; ++rr) {
        int row = wid * 8 + rr;
        const float* pr = g_pre + (size_t)(b0 + row) * 384;
        float s1 = 0.f, s2 = 0.f;
        #pragma unroll
        for (int t = 0; t < 12; ++t) {
            float v = pr[lane + 32 * t];
            s1 += v; s2 = fmaf(v, v, s2);
        }
        #pragma unroll
        for (int off = 16; off; off >>= 1) {
            s1 += __shfl_xor_sync(0xffffffffu, s1, off);
            s2 += __shfl_xor_sync(0xffffffffu, s2, off);
        }
        if (lane == 0) {
            float mu = s1 * (1.f / 384.f);
            float var = s2 * (1.f / 384.f) - mu * mu;
            smu[row] = mu;
            sinv[row] = rsqrtf(var + 1e-5f);
        }
    }
    __syncthreads();

    float areg[8]; float4 breg[4];
    #define LOADB4(W, KS, KT)                                                  \
        _Pragma("unroll")                                                      \
        for (int jj = 0; jj < 4; ++jj) {                                       \
            int qidx = tid + 256 * jj, col = qidx >> 3, q = qidx & 7;          \
            breg[jj] = *(const float4*)&(W)[(size_t)col * (KS) + (KT) + q * 4]; \
        }
    #define STSB4()                                                            \
        _Pragma("unroll")                                                      \
        for (int jj = 0; jj < 4; ++jj) {                                       \
            int qidx = tid + 256 * jj, col = qidx >> 3, q = qidx & 7;          \
            float4 v = breg[jj];                                               \
            v.x = __uint_as_float(tf32cvt(v.x)); v.y = __uint_as_float(tf32cvt(v.y)); \
            v.z = __uint_as_float(tf32cvt(v.z)); v.w = __uint_as_float(tf32cvt(v.w)); \
            *(float4*)&sbt[col * 36 + q * 4] = v;                              \
        }
    #define LOADA_X(KT) do {                                                   \
        int k_ = (KT) + kk;                                                    \
        if (k_ < 384) {                                                        \
            _Pragma("unroll")                                                  \
            for (int j = 0; j < 8; ++j)                                        \
                areg[j] = g_pre[(size_t)(b0 + row0 + 8 * j) * 384 + k_];       \
        } else {                                                               \
            int d_ = k_ - 384;                                                 \
            _Pragma("unroll")                                                  \
            for (int j = 0; j < 8; ++j)                                        \
                areg[j] = src[(size_t)(b0 + row0 + 8 * j) * 128 + d_];         \
        } } while (0)
    #define STSA_X(KT) do {                                                    \
        int k_ = (KT) + kk;                                                    \
        if (k_ < 384) {                                                        \
            float lng = ln_g[k_], lnb = ln_b[k_];                              \
            _Pragma("unroll")                                                  \
            for (int j = 0; j < 8; ++j) {                                      \
                int row = row0 + 8 * j;                                        \
                float v = (areg[j] - smu[row]) * sinv[row] * lng + lnb;        \
                saf[row * 36 + kk] = __uint_as_float(tf32cvt(v));              \
            }                                                                  \
        } else {                                                               \
            _Pragma("unroll")                                                  \
            for (int j = 0; j < 8; ++j)                                        \
                saf[(row0 + 8 * j) * 36 + kk] = __uint_as_float(tf32cvt(areg[j])); \
        } } while (0)

    const int grp = lane >> 2, tig = lane & 3;
    const int rslab = (wid >> 1) * 16, chalf = (wid & 1) * 64;
    const int r0 = rslab + grp;

    // GEMM1: h(64x128) = relu(xln(64x512) @ m1_w^T + b1), 16 K-tiles
    LOADA_X(0); LOADB4(m1_w, 512, 0);
    float acc[32] = {};
    for (int t = 0; t < 16; ++t) {
        __syncthreads();
        STSA_X(t * 32); STSB4();
        __syncthreads();
        if (t < 15) { LOADA_X((t + 1) * 32); LOADB4(m1_w, 512, (t + 1) * 32); }
        mma_warp<8>(acc, saf + rslab * 36, sbt + chalf * 36, lane);
    }
    // relu+bias -> hst (tf32), organized as 4 K-tile A buffers
    #pragma unroll
    for (int nt = 0; nt < 8; ++nt) {
        int col = chalf + nt * 8 + tig * 2;
        float b1a = m1_b[col], b1b = m1_b[col + 1];
        float* hb = hst + (col >> 5) * 2304 + (col & 31);
        hb[r0 * 36]           = __uint_as_float(tf32cvt(fmaxf(acc[nt*4+0] + b1a, 0.f)));
        hb[r0 * 36 + 1]       = __uint_as_float(tf32cvt(fmaxf(acc[nt*4+1] + b1b, 0.f)));
        hb[(r0 + 8) * 36]     = __uint_as_float(tf32cvt(fmaxf(acc[nt*4+2] + b1a, 0.f)));
        hb[(r0 + 8) * 36 + 1] = __uint_as_float(tf32cvt(fmaxf(acc[nt*4+3] + b1b, 0.f)));
    }
    #pragma unroll
    for (int i = 0; i < 32; ++i) acc[i] = 0.f;

    // GEMM2: y(64x128) = h @ m2_w^T + b2, 4 K-tiles
    for (int t = 0; t < 4; ++t) {
        LOADB4(m2_w, 128, t * 32);
        __syncthreads();
        STSB4();
        __syncthreads();
        mma_warp<8>(acc, hst + t * 2304 + rslab * 36, sbt + chalf * 36, lane);
    }
    #pragma unroll
    for (int nt = 0; nt < 8; ++nt) {
        int col = chalf + nt * 8 + tig * 2;
        float b2a = m2_b[col], b2b = m2_b[col + 1];
        *(float2*)&y[(size_t)(b0 + r0) * 128 + col] =
            make_float2(acc[nt*4+0] + b2a, acc[nt*4+1] + b2b);
        *(float2*)&y[(size_t)(b0 + r0 + 8) * 128 + col] =
            make_float2(acc[nt*4+2] + b2a, acc[nt*4+3] + b2b);
    }
    #undef LOADB4
    #undef STSB4
    #undef LOADA_X
    #undef STSA_X
}

// ---------------- launch ----------------
extern "C" void kernel_launch(void* const* d_in, const int* in_sizes, int n_in,
                              void* d_out, int out_size) {
    const float* src    = (const float*)d_in[0];
    const float* seq    = (const float*)d_in[1];
    const float* seq_e  = (const float*)d_in[2];
    const float* src_ts = (const float*)d_in[3];
    const float* seq_ts = (const float*)d_in[4];
    const unsigned int* mask = (const unsigned int*)d_in[5];
    const float* freq   = (const float*)d_in[6];
    const float* phase  = (const float*)d_in[7];
    const float* Wq     = (const float*)d_in[8];
    const float* Wk     = (const float*)d_in[9];
    const float* Wv     = (const float*)d_in[10];
    const float* fc_w   = (const float*)d_in[11];
    const float* fc_b   = (const float*)d_in[12];
    const float* ln_g   = (const float*)d_in[13];
    const float* ln_b   = (const float*)d_in[14];
    const float* m1_w   = (const float*)d_in[15];
    const float* m1_b   = (const float*)d_in[16];
    const float* m2_w   = (const float*)d_in[17];
    const float* m2_b   = (const float*)d_in[18];

    float* y_out = (float*)d_out;
    float* attn_out = y_out + (size_t)BB * DD;

    const int mlp_smem = (2304 + 4608 + 4 * 2304 + 128) * 4;   // 65024
    cudaFuncSetAttribute(k_mlp, cudaFuncAttributeMaxDynamicSharedMemorySize, mlp_smem);

    k_prepm <<<192, 256>>>(Wq, Wk);
    k_qt    <<<2048, 256>>>(src, src_ts, freq, phase);
    k_attn  <<<BB, 256>>>(seq, seq_e, seq_ts, mask, freq, phase, attn_out);
    k_vout  <<<512, 256>>>(Wv);
    k_fc    <<<512, 256>>>(src, src_ts, freq, phase, fc_w, fc_b);
    k_mlp   <<<256, 256, mlp_smem>>>(src, ln_g, ln_b, m1_w, m1_b, m2_w, m2_b, y_out);
}